// round 4
// baseline (speedup 1.0000x reference)
#include <cuda_runtime.h>
#include <cuda_fp16.h>
#include <cstdint>

#define NN     100000
#define HH     128
#define TT     32
#define MDIM   16
#define ES     600000
#define ED     600000

typedef unsigned long long u64;

// ---------------- scratch ----------------
__device__ __align__(16) __half g_Ps[NN * TT];   // fp16 node projections
__device__ __align__(16) __half g_Pd[NN * TT];
__device__ float g_ew_s[ES];
__device__ float g_ew_d[ED];
__device__ __align__(16) float g_mpos[2][NN * MDIM];
__device__ __align__(16) float g_mdom[2][NN * MDIM];

// ---------------- helpers ----------------
__device__ __forceinline__ u64 pack2(float lo, float hi) {
    u64 r; asm("mov.b64 %0, {%1, %2};" : "=l"(r) : "f"(lo), "f"(hi)); return r;
}
__device__ __forceinline__ void unpack2(u64 v, float& lo, float& hi) {
    asm("mov.b64 {%0, %1}, %2;" : "=f"(lo), "=f"(hi) : "l"(v));
}
__device__ __forceinline__ u64 fma2(u64 a, u64 b, u64 c) {
    u64 d; asm("fma.rn.f32x2 %0, %1, %2, %3;" : "=l"(d) : "l"(a), "l"(b), "l"(c)); return d;
}
__device__ __forceinline__ float fast_tanh(float s) {
    float r; asm("tanh.approx.f32 %0, %1;" : "=f"(r) : "f"(s)); return r;
}

// ---------------- kernel 1: node projections (2 nodes/thread, f32x2) ------
__global__ void __launch_bounds__(128) proj_kernel(const float* __restrict__ x,
                                                   const float* __restrict__ Wt) {
    __shared__ __align__(16) float Ws[2 * HH * TT];
    for (int i = threadIdx.x; i < 2 * HH * TT; i += blockDim.x) Ws[i] = Wt[i];
    __syncthreads();
    const u64* WsS = reinterpret_cast<const u64*>(Ws);
    const u64* WsD = reinterpret_cast<const u64*>(Ws + HH * TT);

    int n0 = (blockIdx.x * blockDim.x + threadIdx.x) * 2;
    if (n0 >= NN) return;

    u64 aS0[TT / 2], aS1[TT / 2], aD0[TT / 2], aD1[TT / 2];
#pragma unroll
    for (int t = 0; t < TT / 2; t++) { aS0[t] = 0; aS1[t] = 0; aD0[t] = 0; aD1[t] = 0; }

    const float4* xa = reinterpret_cast<const float4*>(x + (size_t)n0 * HH);
    const float4* xb = reinterpret_cast<const float4*>(x + (size_t)(n0 + 1) * HH);

    for (int h4 = 0; h4 < HH / 4; h4++) {
        float4 va = xa[h4];
        float4 vb = xb[h4];
        float fa[4] = {va.x, va.y, va.z, va.w};
        float fb[4] = {vb.x, vb.y, vb.z, vb.w};
#pragma unroll
        for (int j = 0; j < 4; j++) {
            int h = h4 * 4 + j;
            u64 xa2 = pack2(fa[j], fa[j]);
            u64 xb2 = pack2(fb[j], fb[j]);
            const u64* wS = &WsS[h * (TT / 2)];
            const u64* wD = &WsD[h * (TT / 2)];
#pragma unroll
            for (int t = 0; t < TT / 2; t++) {
                u64 ws = wS[t], wd = wD[t];
                aS0[t] = fma2(xa2, ws, aS0[t]);
                aS1[t] = fma2(xb2, ws, aS1[t]);
                aD0[t] = fma2(xa2, wd, aD0[t]);
                aD1[t] = fma2(xb2, wd, aD1[t]);
            }
        }
    }

    // convert fp32 accumulators -> fp16 rows (32 halves = 64B = 4 x uint4... 2 x uint4 per 16 halves)
    __half2 hs[TT / 2];
    auto store_row = [&](u64* acc, __half* base) {
#pragma unroll
        for (int t = 0; t < TT / 2; t++) {
            float lo, hi; unpack2(acc[t], lo, hi);
            hs[t] = __floats2half2_rn(lo, hi);
        }
        uint4* dst4 = reinterpret_cast<uint4*>(base);
        const uint4* src4 = reinterpret_cast<const uint4*>(hs);
#pragma unroll
        for (int q = 0; q < TT / 8; q++) dst4[q] = src4[q];
    };
    store_row(aS0, &g_Ps[(size_t)n0 * TT]);
    store_row(aS1, &g_Ps[(size_t)(n0 + 1) * TT]);
    store_row(aD0, &g_Pd[(size_t)n0 * TT]);
    store_row(aD1, &g_Pd[(size_t)(n0 + 1) * TT]);
}

// ---------------- kernel 2: per-edge gate (4 lanes/edge, fp16 gathers) ----
__global__ void ew_kernel(const int* __restrict__ si, const int* __restrict__ di,
                          const float* __restrict__ sattr, const float* __restrict__ dattr,
                          const float* __restrict__ b_trans,
                          const float* __restrict__ Wpos, const float* __restrict__ bpos,
                          const float* __restrict__ Wdom, const float* __restrict__ bdom) {
    long long gid = (long long)blockIdx.x * blockDim.x + threadIdx.x;
    long long eg = gid >> 2;       // edge id across both sets
    int sub = (int)(gid & 3);      // 4-lane subgroup: 8 channels each
    if (eg >= (long long)(ES + ED)) return;

    bool spatial = (eg < ES);
    int e = spatial ? (int)eg : (int)(eg - ES);
    const int* eidx = spatial ? si : di;
    int nE = spatial ? ES : ED;
    int src = eidx[e];
    int dst = eidx[nE + e];

    // 8 halves (16B) per lane from each projection row
    uint4 psr = *reinterpret_cast<const uint4*>(&g_Ps[(size_t)src * TT + sub * 8]);
    uint4 pdr = *reinterpret_cast<const uint4*>(&g_Pd[(size_t)dst * TT + sub * 8]);
    const __half2* ph = reinterpret_cast<const __half2*>(&psr);
    const __half2* qh = reinterpret_cast<const __half2*>(&pdr);

    float th[8];
#pragma unroll
    for (int j = 0; j < 4; j++) {
        float2 a = __half22float2(ph[j]);
        float2 b = __half22float2(qh[j]);
        float bt0 = b_trans[sub * 8 + 2 * j];
        float bt1 = b_trans[sub * 8 + 2 * j + 1];
        th[2 * j]     = fast_tanh(a.x + b.x + bt0);
        th[2 * j + 1] = fast_tanh(a.y + b.y + bt1);
    }

    float part = 0.f;
    if (spatial) {
        const float* w = &Wpos[4 + sub * 8];
#pragma unroll
        for (int j = 0; j < 8; j++) part += th[j] * w[j];
        if (sub == 0) {
            float4 a = *reinterpret_cast<const float4*>(&sattr[(size_t)e * 4]);
            part += a.x * Wpos[0] + a.y * Wpos[1] + a.z * Wpos[2] + a.w * Wpos[3];
        }
    } else {
        const float* w = &Wdom[1 + sub * 8];
#pragma unroll
        for (int j = 0; j < 8; j++) part += th[j] * w[j];
        if (sub == 0) part += dattr[e] * Wdom[0];
    }

    part += __shfl_xor_sync(0xFFFFFFFFu, part, 1);
    part += __shfl_xor_sync(0xFFFFFFFFu, part, 2);

    if (sub == 0) {
        float logit = part + (spatial ? bpos[0] : bdom[0]);
        float ew = 1.f / (1.f + __expf(-logit));
        if (spatial) g_ew_s[e] = ew; else g_ew_d[e] = ew;
    }
}

// ---------------- kernel 3: round-0 copy: mask -> all four buffers --------
__global__ void copy0_kernel(const float* __restrict__ mask) {
    int i = blockIdx.x * blockDim.x + threadIdx.x;
    const int n4 = NN * MDIM / 4;
    if (i >= n4) return;
    float4 v = reinterpret_cast<const float4*>(mask)[i];
    reinterpret_cast<float4*>(g_mpos[0])[i] = v;
    reinterpret_cast<float4*>(g_mpos[1])[i] = v;
    reinterpret_cast<float4*>(g_mdom[0])[i] = v;
    reinterpret_cast<float4*>(g_mdom[1])[i] = v;
}

// ---------------- kernel 4: copy m_cur -> m_next --------------------------
__global__ void copy_kernel(int cur) {
    int i = blockIdx.x * blockDim.x + threadIdx.x;
    const int n4 = NN * MDIM / 4;
    if (i >= n4) return;
    int nxt = cur ^ 1;
    reinterpret_cast<float4*>(g_mpos[nxt])[i] = reinterpret_cast<const float4*>(g_mpos[cur])[i];
    reinterpret_cast<float4*>(g_mdom[nxt])[i] = reinterpret_cast<const float4*>(g_mdom[cur])[i];
}

// ---------------- kernel 5: propagation round (1 thread/edge) -------------
// Filter: nxt (or final-max closure) only needs updates where v > m_cur[dst].
__global__ void prop_kernel(const int* __restrict__ si, const int* __restrict__ di, int cur) {
    long long e = (long long)blockIdx.x * blockDim.x + threadIdx.x;
    if (e >= (long long)(ES + ED)) return;
    int nxt = cur ^ 1;

    const float* mc;
    float* mn;
    int src, dst;
    float ew;
    if (e < ES) {
        int ei = (int)e;
        src = si[ei]; dst = si[ES + ei];
        ew = g_ew_s[ei];
        mc = g_mpos[cur]; mn = g_mpos[nxt];
    } else {
        int ei = (int)(e - ES);
        src = di[ei]; dst = di[ED + ei];
        ew = g_ew_d[ei];
        mc = g_mdom[cur]; mn = g_mdom[nxt];
    }

    const float4* sr = reinterpret_cast<const float4*>(&mc[(size_t)src * MDIM]);
    const float4* dr = reinterpret_cast<const float4*>(&mc[(size_t)dst * MDIM]);
    unsigned int* dn = reinterpret_cast<unsigned int*>(&mn[(size_t)dst * MDIM]);

#pragma unroll
    for (int q = 0; q < 4; q++) {
        float4 s = sr[q];
        float4 d = dr[q];
        float v0 = s.x * ew, v1 = s.y * ew, v2 = s.z * ew, v3 = s.w * ew;
        if (v0 > d.x) atomicMax(dn + 4 * q + 0, __float_as_uint(v0));
        if (v1 > d.y) atomicMax(dn + 4 * q + 1, __float_as_uint(v1));
        if (v2 > d.z) atomicMax(dn + 4 * q + 2, __float_as_uint(v2));
        if (v3 > d.w) atomicMax(dn + 4 * q + 3, __float_as_uint(v3));
    }
}

// ---------------- kernel 6: final max over both buffers per branch --------
// Last round skipped its copy: its atomics landed in the stale (m1) buffer,
// filtered against m2. max over both buffers reconstructs m3 exactly
// (older states are dominated by newer ones).
__global__ void final_kernel(const float* __restrict__ mask, float* __restrict__ out) {
    int i = blockIdx.x * blockDim.x + threadIdx.x;
    const int n4 = NN * MDIM / 4;
    if (i >= n4) return;
    float4 m  = reinterpret_cast<const float4*>(mask)[i];
    float4 p0 = reinterpret_cast<const float4*>(g_mpos[0])[i];
    float4 p1 = reinterpret_cast<const float4*>(g_mpos[1])[i];
    float4 d0 = reinterpret_cast<const float4*>(g_mdom[0])[i];
    float4 d1 = reinterpret_cast<const float4*>(g_mdom[1])[i];
    float4 r;
    r.x = fmaxf(fmaxf(m.x, fmaxf(p0.x, p1.x)), fmaxf(d0.x, d1.x));
    r.y = fmaxf(fmaxf(m.y, fmaxf(p0.y, p1.y)), fmaxf(d0.y, d1.y));
    r.z = fmaxf(fmaxf(m.z, fmaxf(p0.z, p1.z)), fmaxf(d0.z, d1.z));
    r.w = fmaxf(fmaxf(m.w, fmaxf(p0.w, p1.w)), fmaxf(d0.w, d1.w));
    reinterpret_cast<float4*>(out)[i] = r;
}

// ---------------- launch -------------------------------------------------
extern "C" void kernel_launch(void* const* d_in, const int* in_sizes, int n_in,
                              void* d_out, int out_size) {
    const float* x     = (const float*)d_in[0];
    const float* mask  = (const float*)d_in[1];
    const int*   si    = (const int*)d_in[2];
    const int*   di    = (const int*)d_in[3];
    const float* sattr = (const float*)d_in[4];
    const float* dattr = (const float*)d_in[5];
    const float* Wt    = (const float*)d_in[6];
    const float* bt    = (const float*)d_in[7];
    const float* Wpos  = (const float*)d_in[8];
    const float* bpos  = (const float*)d_in[9];
    const float* Wdom  = (const float*)d_in[10];
    const float* bdom  = (const float*)d_in[11];
    float* out = (float*)d_out;

    const int n4 = NN * MDIM / 4;

    // 1. node projections (fp16 output)
    proj_kernel<<<(NN / 2 + 127) / 128, 128>>>(x, Wt);

    // 2. round-0 copy: mask -> all four mask buffers
    copy0_kernel<<<(n4 + 255) / 256, 256>>>(mask);

    // 3. per-edge gates: 4 lanes/edge
    {
        long long threads = (long long)(ES + ED) * 4;
        int blk = 256;
        long long grid = (threads + blk - 1) / blk;
        ew_kernel<<<(unsigned)grid, blk>>>(si, di, sattr, dattr, bt, Wpos, bpos, Wdom, bdom);
    }

    // 4. propagation: round 0 (buffers pre-copied), round 1 (copy+prop),
    //    round 2 (NO copy -- reconciled in final)
    {
        long long threads = (long long)(ES + ED);
        int blk = 256;
        long long grid = (threads + blk - 1) / blk;

        prop_kernel<<<(unsigned)grid, blk>>>(si, di, 0);   // m1 -> buf1
        copy_kernel<<<(n4 + 255) / 256, 256>>>(1);          // buf0 = m1
        prop_kernel<<<(unsigned)grid, blk>>>(si, di, 1);   // m2 -> buf0
        prop_kernel<<<(unsigned)grid, blk>>>(si, di, 0);   // agg(m2) -> buf1 (stale m1)
    }

    // 5. final: max over mask + both buffers of each branch
    final_kernel<<<(n4 + 255) / 256, 256>>>(mask, out);
}

// round 5
// speedup vs baseline: 1.3265x; 1.3265x over previous
#include <cuda_runtime.h>
#include <cuda_fp16.h>
#include <cstdint>

#define NN     100000
#define HH     128
#define TT     32
#define MDIM   16
#define ES     600000
#define ED     600000

typedef unsigned long long u64;

// ---------------- scratch ----------------
__device__ __align__(16) __half g_Ps[NN * TT];   // fp16 node projections
__device__ __align__(16) __half g_Pd[NN * TT];
__device__ float g_ew_s[ES];
__device__ float g_ew_d[ED];
__device__ __align__(16) float g_mpos[2][NN * MDIM];
__device__ __align__(16) float g_mdom[2][NN * MDIM];

// ---------------- helpers ----------------
__device__ __forceinline__ u64 pack2(float lo, float hi) {
    u64 r; asm("mov.b64 %0, {%1, %2};" : "=l"(r) : "f"(lo), "f"(hi)); return r;
}
__device__ __forceinline__ void unpack2(u64 v, float& lo, float& hi) {
    asm("mov.b64 {%0, %1}, %2;" : "=f"(lo), "=f"(hi) : "l"(v));
}
__device__ __forceinline__ u64 fma2(u64 a, u64 b, u64 c) {
    u64 d; asm("fma.rn.f32x2 %0, %1, %2, %3;" : "=l"(d) : "l"(a), "l"(b), "l"(c)); return d;
}
__device__ __forceinline__ float fast_tanh(float s) {
    float r; asm("tanh.approx.f32 %0, %1;" : "=f"(r) : "f"(s)); return r;
}

// ---------------- kernel 1: node projections (2 nodes/thread, f32x2) ------
__global__ void __launch_bounds__(128) proj_kernel(const float* __restrict__ x,
                                                   const float* __restrict__ Wt) {
    __shared__ __align__(16) float Ws[2 * HH * TT];
    for (int i = threadIdx.x; i < 2 * HH * TT; i += blockDim.x) Ws[i] = Wt[i];
    __syncthreads();
    const u64* WsS = reinterpret_cast<const u64*>(Ws);
    const u64* WsD = reinterpret_cast<const u64*>(Ws + HH * TT);

    int n0 = (blockIdx.x * blockDim.x + threadIdx.x) * 2;
    if (n0 >= NN) return;

    u64 aS0[TT / 2], aS1[TT / 2], aD0[TT / 2], aD1[TT / 2];
#pragma unroll
    for (int t = 0; t < TT / 2; t++) { aS0[t] = 0; aS1[t] = 0; aD0[t] = 0; aD1[t] = 0; }

    const float4* xa = reinterpret_cast<const float4*>(x + (size_t)n0 * HH);
    const float4* xb = reinterpret_cast<const float4*>(x + (size_t)(n0 + 1) * HH);

    for (int h4 = 0; h4 < HH / 4; h4++) {
        float4 va = xa[h4];
        float4 vb = xb[h4];
        float fa[4] = {va.x, va.y, va.z, va.w};
        float fb[4] = {vb.x, vb.y, vb.z, vb.w};
#pragma unroll
        for (int j = 0; j < 4; j++) {
            int h = h4 * 4 + j;
            u64 xa2 = pack2(fa[j], fa[j]);
            u64 xb2 = pack2(fb[j], fb[j]);
            const u64* wS = &WsS[h * (TT / 2)];
            const u64* wD = &WsD[h * (TT / 2)];
#pragma unroll
            for (int t = 0; t < TT / 2; t++) {
                u64 ws = wS[t], wd = wD[t];
                aS0[t] = fma2(xa2, ws, aS0[t]);
                aS1[t] = fma2(xb2, ws, aS1[t]);
                aD0[t] = fma2(xa2, wd, aD0[t]);
                aD1[t] = fma2(xb2, wd, aD1[t]);
            }
        }
    }

    __half2 hs[TT / 2];
    auto store_row = [&](u64* acc, __half* base) {
#pragma unroll
        for (int t = 0; t < TT / 2; t++) {
            float lo, hi; unpack2(acc[t], lo, hi);
            hs[t] = __floats2half2_rn(lo, hi);
        }
        uint4* dst4 = reinterpret_cast<uint4*>(base);
        const uint4* src4 = reinterpret_cast<const uint4*>(hs);
#pragma unroll
        for (int q = 0; q < TT / 8; q++) dst4[q] = src4[q];
    };
    store_row(aS0, &g_Ps[(size_t)n0 * TT]);
    store_row(aS1, &g_Ps[(size_t)(n0 + 1) * TT]);
    store_row(aD0, &g_Pd[(size_t)n0 * TT]);
    store_row(aD1, &g_Pd[(size_t)(n0 + 1) * TT]);
}

// ---------------- kernel 2: per-edge gate (4 lanes/edge, fp16 gathers) ----
__global__ void ew_kernel(const int* __restrict__ si, const int* __restrict__ di,
                          const float* __restrict__ sattr, const float* __restrict__ dattr,
                          const float* __restrict__ b_trans,
                          const float* __restrict__ Wpos, const float* __restrict__ bpos,
                          const float* __restrict__ Wdom, const float* __restrict__ bdom) {
    long long gid = (long long)blockIdx.x * blockDim.x + threadIdx.x;
    long long eg = gid >> 2;
    int sub = (int)(gid & 3);
    if (eg >= (long long)(ES + ED)) return;

    bool spatial = (eg < ES);
    int e = spatial ? (int)eg : (int)(eg - ES);
    const int* eidx = spatial ? si : di;
    int nE = spatial ? ES : ED;
    int src = eidx[e];
    int dst = eidx[nE + e];

    uint4 psr = *reinterpret_cast<const uint4*>(&g_Ps[(size_t)src * TT + sub * 8]);
    uint4 pdr = *reinterpret_cast<const uint4*>(&g_Pd[(size_t)dst * TT + sub * 8]);
    const __half2* ph = reinterpret_cast<const __half2*>(&psr);
    const __half2* qh = reinterpret_cast<const __half2*>(&pdr);

    float th[8];
#pragma unroll
    for (int j = 0; j < 4; j++) {
        float2 a = __half22float2(ph[j]);
        float2 b = __half22float2(qh[j]);
        float bt0 = b_trans[sub * 8 + 2 * j];
        float bt1 = b_trans[sub * 8 + 2 * j + 1];
        th[2 * j]     = fast_tanh(a.x + b.x + bt0);
        th[2 * j + 1] = fast_tanh(a.y + b.y + bt1);
    }

    float part = 0.f;
    if (spatial) {
        const float* w = &Wpos[4 + sub * 8];
#pragma unroll
        for (int j = 0; j < 8; j++) part += th[j] * w[j];
        if (sub == 0) {
            float4 a = *reinterpret_cast<const float4*>(&sattr[(size_t)e * 4]);
            part += a.x * Wpos[0] + a.y * Wpos[1] + a.z * Wpos[2] + a.w * Wpos[3];
        }
    } else {
        const float* w = &Wdom[1 + sub * 8];
#pragma unroll
        for (int j = 0; j < 8; j++) part += th[j] * w[j];
        if (sub == 0) part += dattr[e] * Wdom[0];
    }

    part += __shfl_xor_sync(0xFFFFFFFFu, part, 1);
    part += __shfl_xor_sync(0xFFFFFFFFu, part, 2);

    if (sub == 0) {
        float logit = part + (spatial ? bpos[0] : bdom[0]);
        float ew = 1.f / (1.f + __expf(-logit));
        if (spatial) g_ew_s[e] = ew; else g_ew_d[e] = ew;
    }
}

// ---------------- kernel 3: round-0 copy: mask -> all four buffers --------
__global__ void copy0_kernel(const float* __restrict__ mask) {
    int i = blockIdx.x * blockDim.x + threadIdx.x;
    const int n4 = NN * MDIM / 4;
    if (i >= n4) return;
    float4 v = reinterpret_cast<const float4*>(mask)[i];
    reinterpret_cast<float4*>(g_mpos[0])[i] = v;
    reinterpret_cast<float4*>(g_mpos[1])[i] = v;
    reinterpret_cast<float4*>(g_mdom[0])[i] = v;
    reinterpret_cast<float4*>(g_mdom[1])[i] = v;
}

// ---------------- kernel 4: copy m_cur -> m_next --------------------------
__global__ void copy_kernel(int cur) {
    int i = blockIdx.x * blockDim.x + threadIdx.x;
    const int n4 = NN * MDIM / 4;
    if (i >= n4) return;
    int nxt = cur ^ 1;
    reinterpret_cast<float4*>(g_mpos[nxt])[i] = reinterpret_cast<const float4*>(g_mpos[cur])[i];
    reinterpret_cast<float4*>(g_mdom[nxt])[i] = reinterpret_cast<const float4*>(g_mdom[cur])[i];
}

// ---------------- kernel 5: propagation (4 threads/edge, filtered) --------
// 4 consecutive lanes cover one edge's 64B row -> L1 coalesces into one
// wavefront per row instead of 4. idx/ew loads broadcast within the quad.
__global__ void prop_kernel(const int* __restrict__ si, const int* __restrict__ di, int cur) {
    long long t = (long long)blockIdx.x * blockDim.x + threadIdx.x;
    long long q = t >> 2;            // edge id across both sets
    int c4 = (int)(t & 3);           // channel quad 0..3
    if (q >= (long long)(ES + ED)) return;
    int nxt = cur ^ 1;

    const float* mc;
    float* mn;
    int src, dst;
    float ew;
    if (q < ES) {
        int ei = (int)q;
        src = si[ei]; dst = si[ES + ei];
        ew = g_ew_s[ei];
        mc = g_mpos[cur]; mn = g_mpos[nxt];
    } else {
        int ei = (int)(q - ES);
        src = di[ei]; dst = di[ED + ei];
        ew = g_ew_d[ei];
        mc = g_mdom[cur]; mn = g_mdom[nxt];
    }

    float4 s = *reinterpret_cast<const float4*>(&mc[(size_t)src * MDIM + c4 * 4]);
    float4 d = *reinterpret_cast<const float4*>(&mc[(size_t)dst * MDIM + c4 * 4]);
    unsigned int* dn = reinterpret_cast<unsigned int*>(&mn[(size_t)dst * MDIM + c4 * 4]);

    float v0 = s.x * ew, v1 = s.y * ew, v2 = s.z * ew, v3 = s.w * ew;
    if (v0 > d.x) atomicMax(dn + 0, __float_as_uint(v0));
    if (v1 > d.y) atomicMax(dn + 1, __float_as_uint(v1));
    if (v2 > d.z) atomicMax(dn + 2, __float_as_uint(v2));
    if (v3 > d.w) atomicMax(dn + 3, __float_as_uint(v3));
}

// ---------------- kernel 6: final max over both buffers per branch --------
__global__ void final_kernel(const float* __restrict__ mask, float* __restrict__ out) {
    int i = blockIdx.x * blockDim.x + threadIdx.x;
    const int n4 = NN * MDIM / 4;
    if (i >= n4) return;
    float4 m  = reinterpret_cast<const float4*>(mask)[i];
    float4 p0 = reinterpret_cast<const float4*>(g_mpos[0])[i];
    float4 p1 = reinterpret_cast<const float4*>(g_mpos[1])[i];
    float4 d0 = reinterpret_cast<const float4*>(g_mdom[0])[i];
    float4 d1 = reinterpret_cast<const float4*>(g_mdom[1])[i];
    float4 r;
    r.x = fmaxf(fmaxf(m.x, fmaxf(p0.x, p1.x)), fmaxf(d0.x, d1.x));
    r.y = fmaxf(fmaxf(m.y, fmaxf(p0.y, p1.y)), fmaxf(d0.y, d1.y));
    r.z = fmaxf(fmaxf(m.z, fmaxf(p0.z, p1.z)), fmaxf(d0.z, d1.z));
    r.w = fmaxf(fmaxf(m.w, fmaxf(p0.w, p1.w)), fmaxf(d0.w, d1.w));
    reinterpret_cast<float4*>(out)[i] = r;
}

// ---------------- launch -------------------------------------------------
extern "C" void kernel_launch(void* const* d_in, const int* in_sizes, int n_in,
                              void* d_out, int out_size) {
    const float* x     = (const float*)d_in[0];
    const float* mask  = (const float*)d_in[1];
    const int*   si    = (const int*)d_in[2];
    const int*   di    = (const int*)d_in[3];
    const float* sattr = (const float*)d_in[4];
    const float* dattr = (const float*)d_in[5];
    const float* Wt    = (const float*)d_in[6];
    const float* bt    = (const float*)d_in[7];
    const float* Wpos  = (const float*)d_in[8];
    const float* bpos  = (const float*)d_in[9];
    const float* Wdom  = (const float*)d_in[10];
    const float* bdom  = (const float*)d_in[11];
    float* out = (float*)d_out;

    const int n4 = NN * MDIM / 4;

    // 1. node projections (fp16 output)
    proj_kernel<<<(NN / 2 + 127) / 128, 128>>>(x, Wt);

    // 2. round-0 copy: mask -> all four mask buffers
    copy0_kernel<<<(n4 + 255) / 256, 256>>>(mask);

    // 3. per-edge gates: 4 lanes/edge
    {
        long long threads = (long long)(ES + ED) * 4;
        int blk = 256;
        long long grid = (threads + blk - 1) / blk;
        ew_kernel<<<(unsigned)grid, blk>>>(si, di, sattr, dattr, bt, Wpos, bpos, Wdom, bdom);
    }

    // 4. propagation: round 0 (buffers pre-copied), round 1 (copy+prop),
    //    round 2 (NO copy -- reconciled in final)
    {
        long long threads = (long long)(ES + ED) * 4;   // 4 threads per edge
        int blk = 256;
        long long grid = (threads + blk - 1) / blk;

        prop_kernel<<<(unsigned)grid, blk>>>(si, di, 0);   // m1 -> buf1
        copy_kernel<<<(n4 + 255) / 256, 256>>>(1);          // buf0 = m1
        prop_kernel<<<(unsigned)grid, blk>>>(si, di, 1);   // m2 -> buf0
        prop_kernel<<<(unsigned)grid, blk>>>(si, di, 0);   // agg(m2) -> buf1 (stale m1)
    }

    // 5. final: max over mask + both buffers of each branch
    final_kernel<<<(n4 + 255) / 256, 256>>>(mask, out);
}

// round 6
// speedup vs baseline: 1.3512x; 1.0186x over previous
#include <cuda_runtime.h>
#include <cuda_fp16.h>
#include <cstdint>

#define NN     100000
#define HH     128
#define TT     32
#define MDIM   16
#define ES     600000
#define ED     600000

typedef unsigned long long u64;

// ---------------- scratch ----------------
__device__ __align__(16) __half g_Ps[NN * TT];   // fp16 node projections
__device__ __align__(16) __half g_Pd[NN * TT];
__device__ float g_ew_s[ES];
__device__ float g_ew_d[ED];
// propagation state: fp32 accumulator (atomics) + fp16 read mirror
__device__ __align__(16) float  g_n32pos[NN * MDIM];
__device__ __align__(16) float  g_n32dom[NN * MDIM];
__device__ __align__(16) __half g_c16pos[NN * MDIM];
__device__ __align__(16) __half g_c16dom[NN * MDIM];

// ---------------- helpers ----------------
__device__ __forceinline__ u64 pack2(float lo, float hi) {
    u64 r; asm("mov.b64 %0, {%1, %2};" : "=l"(r) : "f"(lo), "f"(hi)); return r;
}
__device__ __forceinline__ void unpack2(u64 v, float& lo, float& hi) {
    asm("mov.b64 {%0, %1}, %2;" : "=f"(lo), "=f"(hi) : "l"(v));
}
__device__ __forceinline__ u64 fma2(u64 a, u64 b, u64 c) {
    u64 d; asm("fma.rn.f32x2 %0, %1, %2, %3;" : "=l"(d) : "l"(a), "l"(b), "l"(c)); return d;
}
__device__ __forceinline__ float fast_tanh(float s) {
    float r; asm("tanh.approx.f32 %0, %1;" : "=f"(r) : "f"(s)); return r;
}

// ---------------- kernel 1: node projections (2 nodes/thread, f32x2) ------
__global__ void __launch_bounds__(128) proj_kernel(const float* __restrict__ x,
                                                   const float* __restrict__ Wt) {
    __shared__ __align__(16) float Ws[2 * HH * TT];
    for (int i = threadIdx.x; i < 2 * HH * TT; i += blockDim.x) Ws[i] = Wt[i];
    __syncthreads();
    const u64* WsS = reinterpret_cast<const u64*>(Ws);
    const u64* WsD = reinterpret_cast<const u64*>(Ws + HH * TT);

    int n0 = (blockIdx.x * blockDim.x + threadIdx.x) * 2;
    if (n0 >= NN) return;

    u64 aS0[TT / 2], aS1[TT / 2], aD0[TT / 2], aD1[TT / 2];
#pragma unroll
    for (int t = 0; t < TT / 2; t++) { aS0[t] = 0; aS1[t] = 0; aD0[t] = 0; aD1[t] = 0; }

    const float4* xa = reinterpret_cast<const float4*>(x + (size_t)n0 * HH);
    const float4* xb = reinterpret_cast<const float4*>(x + (size_t)(n0 + 1) * HH);

    for (int h4 = 0; h4 < HH / 4; h4++) {
        float4 va = xa[h4];
        float4 vb = xb[h4];
        float fa[4] = {va.x, va.y, va.z, va.w};
        float fb[4] = {vb.x, vb.y, vb.z, vb.w};
#pragma unroll
        for (int j = 0; j < 4; j++) {
            int h = h4 * 4 + j;
            u64 xa2 = pack2(fa[j], fa[j]);
            u64 xb2 = pack2(fb[j], fb[j]);
            const u64* wS = &WsS[h * (TT / 2)];
            const u64* wD = &WsD[h * (TT / 2)];
#pragma unroll
            for (int t = 0; t < TT / 2; t++) {
                u64 ws = wS[t], wd = wD[t];
                aS0[t] = fma2(xa2, ws, aS0[t]);
                aS1[t] = fma2(xb2, ws, aS1[t]);
                aD0[t] = fma2(xa2, wd, aD0[t]);
                aD1[t] = fma2(xb2, wd, aD1[t]);
            }
        }
    }

    __half2 hs[TT / 2];
    auto store_row = [&](u64* acc, __half* base) {
#pragma unroll
        for (int t = 0; t < TT / 2; t++) {
            float lo, hi; unpack2(acc[t], lo, hi);
            hs[t] = __floats2half2_rn(lo, hi);
        }
        uint4* dst4 = reinterpret_cast<uint4*>(base);
        const uint4* src4 = reinterpret_cast<const uint4*>(hs);
#pragma unroll
        for (int q = 0; q < TT / 8; q++) dst4[q] = src4[q];
    };
    store_row(aS0, &g_Ps[(size_t)n0 * TT]);
    store_row(aS1, &g_Ps[(size_t)(n0 + 1) * TT]);
    store_row(aD0, &g_Pd[(size_t)n0 * TT]);
    store_row(aD1, &g_Pd[(size_t)(n0 + 1) * TT]);
}

// ---------------- kernel 2: per-edge gate (4 lanes/edge, fp16 gathers) ----
__global__ void ew_kernel(const int* __restrict__ si, const int* __restrict__ di,
                          const float* __restrict__ sattr, const float* __restrict__ dattr,
                          const float* __restrict__ b_trans,
                          const float* __restrict__ Wpos, const float* __restrict__ bpos,
                          const float* __restrict__ Wdom, const float* __restrict__ bdom) {
    long long gid = (long long)blockIdx.x * blockDim.x + threadIdx.x;
    long long eg = gid >> 2;
    int sub = (int)(gid & 3);
    if (eg >= (long long)(ES + ED)) return;

    bool spatial = (eg < ES);
    int e = spatial ? (int)eg : (int)(eg - ES);
    const int* eidx = spatial ? si : di;
    int nE = spatial ? ES : ED;
    int src = eidx[e];
    int dst = eidx[nE + e];

    uint4 psr = *reinterpret_cast<const uint4*>(&g_Ps[(size_t)src * TT + sub * 8]);
    uint4 pdr = *reinterpret_cast<const uint4*>(&g_Pd[(size_t)dst * TT + sub * 8]);
    const __half2* ph = reinterpret_cast<const __half2*>(&psr);
    const __half2* qh = reinterpret_cast<const __half2*>(&pdr);

    float th[8];
#pragma unroll
    for (int j = 0; j < 4; j++) {
        float2 a = __half22float2(ph[j]);
        float2 b = __half22float2(qh[j]);
        float bt0 = b_trans[sub * 8 + 2 * j];
        float bt1 = b_trans[sub * 8 + 2 * j + 1];
        th[2 * j]     = fast_tanh(a.x + b.x + bt0);
        th[2 * j + 1] = fast_tanh(a.y + b.y + bt1);
    }

    float part = 0.f;
    if (spatial) {
        const float* w = &Wpos[4 + sub * 8];
#pragma unroll
        for (int j = 0; j < 8; j++) part += th[j] * w[j];
        if (sub == 0) {
            float4 a = *reinterpret_cast<const float4*>(&sattr[(size_t)e * 4]);
            part += a.x * Wpos[0] + a.y * Wpos[1] + a.z * Wpos[2] + a.w * Wpos[3];
        }
    } else {
        const float* w = &Wdom[1 + sub * 8];
#pragma unroll
        for (int j = 0; j < 8; j++) part += th[j] * w[j];
        if (sub == 0) part += dattr[e] * Wdom[0];
    }

    part += __shfl_xor_sync(0xFFFFFFFFu, part, 1);
    part += __shfl_xor_sync(0xFFFFFFFFu, part, 2);

    if (sub == 0) {
        float logit = part + (spatial ? bpos[0] : bdom[0]);
        float ew = 1.f / (1.f + __expf(-logit));
        if (spatial) g_ew_s[e] = ew; else g_ew_d[e] = ew;
    }
}

// ---------------- kernel 3: init: mask -> n32 (fp32) + c16 (fp16) ---------
__global__ void init_kernel(const float* __restrict__ mask) {
    int i = blockIdx.x * blockDim.x + threadIdx.x;   // float4 index
    const int n4 = NN * MDIM / 4;
    if (i >= n4) return;
    float4 v = reinterpret_cast<const float4*>(mask)[i];
    reinterpret_cast<float4*>(g_n32pos)[i] = v;
    reinterpret_cast<float4*>(g_n32dom)[i] = v;
    __half2 h0 = __floats2half2_rn(v.x, v.y);
    __half2 h1 = __floats2half2_rn(v.z, v.w);
    uint2 packed = make_uint2(*reinterpret_cast<unsigned*>(&h0), *reinterpret_cast<unsigned*>(&h1));
    reinterpret_cast<uint2*>(g_c16pos)[i] = packed;
    reinterpret_cast<uint2*>(g_c16dom)[i] = packed;
}

// ---------------- kernel 4: convert n32 -> c16 (both branches) ------------
__global__ void convert_kernel() {
    int i = blockIdx.x * blockDim.x + threadIdx.x;   // float4 index
    const int n4 = NN * MDIM / 4;
    if (i >= n4) return;
    float4 p = reinterpret_cast<const float4*>(g_n32pos)[i];
    float4 d = reinterpret_cast<const float4*>(g_n32dom)[i];
    __half2 p0 = __floats2half2_rn(p.x, p.y);
    __half2 p1 = __floats2half2_rn(p.z, p.w);
    __half2 d0 = __floats2half2_rn(d.x, d.y);
    __half2 d1 = __floats2half2_rn(d.z, d.w);
    reinterpret_cast<uint2*>(g_c16pos)[i] =
        make_uint2(*reinterpret_cast<unsigned*>(&p0), *reinterpret_cast<unsigned*>(&p1));
    reinterpret_cast<uint2*>(g_c16dom)[i] =
        make_uint2(*reinterpret_cast<unsigned*>(&d0), *reinterpret_cast<unsigned*>(&d1));
}

// ---------------- kernel 5: propagation (2 lanes/edge, fp16 reads) --------
// Reads fp16 mirror (32B/row), filters, atomics into the fp32 accumulator.
// Skipping v <= c16[dst] is exact up to one fp16 ulp (same order as read
// rounding); n32 >= every applied update, so no work is lost.
__global__ void prop_kernel(const int* __restrict__ si, const int* __restrict__ di) {
    long long t = (long long)blockIdx.x * blockDim.x + threadIdx.x;
    long long p = t >> 1;            // edge id across both sets
    int sub = (int)(t & 1);          // half-row 0..1 (8 channels each)
    if (p >= (long long)(ES + ED)) return;

    const __half* c;
    float* n;
    int src, dst;
    float ew;
    if (p < ES) {
        int ei = (int)p;
        src = si[ei]; dst = si[ES + ei];
        ew = g_ew_s[ei];
        c = g_c16pos; n = g_n32pos;
    } else {
        int ei = (int)(p - ES);
        src = di[ei]; dst = di[ED + ei];
        ew = g_ew_d[ei];
        c = g_c16dom; n = g_n32dom;
    }

    uint4 sr = *reinterpret_cast<const uint4*>(&c[(size_t)src * MDIM + sub * 8]);
    uint4 dr = *reinterpret_cast<const uint4*>(&c[(size_t)dst * MDIM + sub * 8]);
    const __half2* sh = reinterpret_cast<const __half2*>(&sr);
    const __half2* dh = reinterpret_cast<const __half2*>(&dr);
    unsigned int* dn = reinterpret_cast<unsigned int*>(&n[(size_t)dst * MDIM + sub * 8]);

#pragma unroll
    for (int j = 0; j < 4; j++) {
        float2 s = __half22float2(sh[j]);
        float2 d = __half22float2(dh[j]);
        float v0 = s.x * ew, v1 = s.y * ew;
        if (v0 > d.x) atomicMax(dn + 2 * j + 0, __float_as_uint(v0));
        if (v1 > d.y) atomicMax(dn + 2 * j + 1, __float_as_uint(v1));
    }
}

// ---------------- kernel 6: final max --------------------------------------
__global__ void final_kernel(const float* __restrict__ mask, float* __restrict__ out) {
    int i = blockIdx.x * blockDim.x + threadIdx.x;
    const int n4 = NN * MDIM / 4;
    if (i >= n4) return;
    float4 m = reinterpret_cast<const float4*>(mask)[i];
    float4 p = reinterpret_cast<const float4*>(g_n32pos)[i];
    float4 d = reinterpret_cast<const float4*>(g_n32dom)[i];
    float4 r;
    r.x = fmaxf(m.x, fmaxf(p.x, d.x));
    r.y = fmaxf(m.y, fmaxf(p.y, d.y));
    r.z = fmaxf(m.z, fmaxf(p.z, d.z));
    r.w = fmaxf(m.w, fmaxf(p.w, d.w));
    reinterpret_cast<float4*>(out)[i] = r;
}

// ---------------- launch -------------------------------------------------
extern "C" void kernel_launch(void* const* d_in, const int* in_sizes, int n_in,
                              void* d_out, int out_size) {
    const float* x     = (const float*)d_in[0];
    const float* mask  = (const float*)d_in[1];
    const int*   si    = (const int*)d_in[2];
    const int*   di    = (const int*)d_in[3];
    const float* sattr = (const float*)d_in[4];
    const float* dattr = (const float*)d_in[5];
    const float* Wt    = (const float*)d_in[6];
    const float* bt    = (const float*)d_in[7];
    const float* Wpos  = (const float*)d_in[8];
    const float* bpos  = (const float*)d_in[9];
    const float* Wdom  = (const float*)d_in[10];
    const float* bdom  = (const float*)d_in[11];
    float* out = (float*)d_out;

    const int n4 = NN * MDIM / 4;

    // 1. node projections (fp16 output)
    proj_kernel<<<(NN / 2 + 127) / 128, 128>>>(x, Wt);

    // 2. init: mask -> fp32 accumulators + fp16 mirrors
    init_kernel<<<(n4 + 255) / 256, 256>>>(mask);

    // 3. per-edge gates: 4 lanes/edge
    {
        long long threads = (long long)(ES + ED) * 4;
        int blk = 256;
        long long grid = (threads + blk - 1) / blk;
        ew_kernel<<<(unsigned)grid, blk>>>(si, di, sattr, dattr, bt, Wpos, bpos, Wdom, bdom);
    }

    // 4. propagation: prop / convert / prop / convert / prop
    {
        long long threads = (long long)(ES + ED) * 2;   // 2 lanes per edge
        int blk = 256;
        long long grid = (threads + blk - 1) / blk;
        int cgrid = (n4 + 255) / 256;

        prop_kernel<<<(unsigned)grid, blk>>>(si, di);
        convert_kernel<<<cgrid, 256>>>();
        prop_kernel<<<(unsigned)grid, blk>>>(si, di);
        convert_kernel<<<cgrid, 256>>>();
        prop_kernel<<<(unsigned)grid, blk>>>(si, di);
    }

    // 5. final: max(mask, pos, dom)
    final_kernel<<<(n4 + 255) / 256, 256>>>(mask, out);
}

// round 7
// speedup vs baseline: 1.7094x; 1.2651x over previous
#include <cuda_runtime.h>
#include <cuda_fp16.h>
#include <cstdint>

#define NN     100000
#define HH     128
#define TT     32
#define MDIM   16
#define ES     600000
#define ED     600000

// ---------------- scratch ----------------
__device__ __align__(16) __half g_Ps[NN * TT];   // fp16 node projections
__device__ __align__(16) __half g_Pd[NN * TT];
__device__ float g_ew_s[ES];
__device__ float g_ew_d[ED];
// propagation state: fp32 accumulator (atomics) + fp16 read mirror
__device__ __align__(16) float  g_n32pos[NN * MDIM];
__device__ __align__(16) float  g_n32dom[NN * MDIM];
__device__ __align__(16) __half g_c16pos[NN * MDIM];
__device__ __align__(16) __half g_c16dom[NN * MDIM];

// ---------------- helpers ----------------
__device__ __forceinline__ float fast_tanh(float s) {
    float r; asm("tanh.approx.f32 %0, %1;" : "=f"(r) : "f"(s)); return r;
}
__device__ __forceinline__ unsigned su32(const void* p) {
    return (unsigned)__cvta_generic_to_shared(p);
}

// ---------------- kernel 1: HMMA node projections --------------------------
// One GEMM: [NN,128] @ [128,64] fp16 (cols 0-31 = W[:128], 32-63 = W[128:]).
// Block = 128 thr = 4 warps; warp does 16 nodes (m16), 8 n-tiles, 8 k-steps.
#define XS_STRIDE 136   // 64 rows of x, padded (272B: ldmatrix conflict-free)
#define WP_STRIDE 72    // 128 rows of W', padded (144B)

__global__ void __launch_bounds__(128) proj_kernel(const float* __restrict__ x,
                                                   const float* __restrict__ Wt) {
    __shared__ __align__(16) __half Wp[128 * WP_STRIDE];
    __shared__ __align__(16) __half xs[64 * XS_STRIDE];
    int tid = threadIdx.x;
    int n0 = blockIdx.x * 64;

    // stage W' fp16
    for (int i = tid; i < 128 * 64; i += 128) {
        int h = i >> 6, j = i & 63;
        float w = (j < 32) ? Wt[h * 32 + j] : Wt[(128 + h) * 32 + (j - 32)];
        Wp[h * WP_STRIDE + j] = __float2half_rn(w);
    }
    // stage x fp16 (64 rows, zero-pad past NN)
    for (int i = tid; i < 64 * 32; i += 128) {    // float4 index
        int r = i >> 5, c4 = i & 31;
        int node = n0 + r;
        float4 v = (node < NN)
                 ? reinterpret_cast<const float4*>(x)[(size_t)node * 32 + c4]
                 : make_float4(0.f, 0.f, 0.f, 0.f);
        *reinterpret_cast<__half2*>(&xs[r * XS_STRIDE + c4 * 4])     = __floats2half2_rn(v.x, v.y);
        *reinterpret_cast<__half2*>(&xs[r * XS_STRIDE + c4 * 4 + 2]) = __floats2half2_rn(v.z, v.w);
    }
    __syncthreads();

    int warp = tid >> 5, lane = tid & 31;
    int wb = warp * 16;

    float acc[8][4];
#pragma unroll
    for (int nt = 0; nt < 8; nt++)
#pragma unroll
        for (int j = 0; j < 4; j++) acc[nt][j] = 0.f;

    int a_row = wb + (lane & 15);
    int a_coff = (lane >> 4) * 8;
    int b_row = (lane & 15);

#pragma unroll
    for (int k = 0; k < 8; k++) {
        unsigned a0, a1, a2, a3;
        unsigned addrA = su32(&xs[a_row * XS_STRIDE + k * 16 + a_coff]);
        asm volatile("ldmatrix.sync.aligned.m8n8.x4.shared.b16 {%0,%1,%2,%3}, [%4];"
                     : "=r"(a0), "=r"(a1), "=r"(a2), "=r"(a3) : "r"(addrA));
#pragma unroll
        for (int nt = 0; nt < 8; nt++) {
            unsigned b0, b1;
            unsigned addrB = su32(&Wp[(k * 16 + b_row) * WP_STRIDE + nt * 8]);
            asm volatile("ldmatrix.sync.aligned.m8n8.x2.trans.shared.b16 {%0,%1}, [%2];"
                         : "=r"(b0), "=r"(b1) : "r"(addrB));
            asm volatile("mma.sync.aligned.m16n8k16.row.col.f32.f16.f16.f32 "
                         "{%0,%1,%2,%3}, {%4,%5,%6,%7}, {%8,%9}, {%0,%1,%2,%3};"
                         : "+f"(acc[nt][0]), "+f"(acc[nt][1]), "+f"(acc[nt][2]), "+f"(acc[nt][3])
                         : "r"(a0), "r"(a1), "r"(a2), "r"(a3), "r"(b0), "r"(b1));
        }
    }

    // write out: lane owns rows (lane/4, lane/4+8), cols (lane%4)*2,+1 of each n-tile
    int row_l = wb + (lane >> 2);
    int col0 = (lane & 3) * 2;
#pragma unroll
    for (int nt = 0; nt < 8; nt++) {
        __half* base = (nt < 4) ? g_Ps : g_Pd;
        int cc = (nt < 4) ? (nt * 8 + col0) : (nt * 8 + col0 - 32);
        int nodeA = n0 + row_l;
        int nodeB = nodeA + 8;
        if (nodeA < NN)
            *reinterpret_cast<__half2*>(&base[(size_t)nodeA * TT + cc]) =
                __floats2half2_rn(acc[nt][0], acc[nt][1]);
        if (nodeB < NN)
            *reinterpret_cast<__half2*>(&base[(size_t)nodeB * TT + cc]) =
                __floats2half2_rn(acc[nt][2], acc[nt][3]);
    }
}

// ---------------- kernel 2: init: mask -> n32 (fp32) + c16 (fp16) ---------
__global__ void init_kernel(const float* __restrict__ mask) {
    int i = blockIdx.x * blockDim.x + threadIdx.x;   // float4 index
    const int n4 = NN * MDIM / 4;
    if (i >= n4) return;
    float4 v = reinterpret_cast<const float4*>(mask)[i];
    reinterpret_cast<float4*>(g_n32pos)[i] = v;
    reinterpret_cast<float4*>(g_n32dom)[i] = v;
    __half2 h0 = __floats2half2_rn(v.x, v.y);
    __half2 h1 = __floats2half2_rn(v.z, v.w);
    uint2 packed = make_uint2(*reinterpret_cast<unsigned*>(&h0), *reinterpret_cast<unsigned*>(&h1));
    reinterpret_cast<uint2*>(g_c16pos)[i] = packed;
    reinterpret_cast<uint2*>(g_c16dom)[i] = packed;
}

// ---------------- kernel 3: FUSED gate + propagation round 1 ---------------
// 4 lanes/edge: compute ew (tanh dot over 32 channels), quad-reduce, store ew,
// then lanes 0-1 immediately do the round-1 filtered max-propagation.
__global__ void ewprop_kernel(const int* __restrict__ si, const int* __restrict__ di,
                              const float* __restrict__ sattr, const float* __restrict__ dattr,
                              const float* __restrict__ b_trans,
                              const float* __restrict__ Wpos, const float* __restrict__ bpos,
                              const float* __restrict__ Wdom, const float* __restrict__ bdom) {
    long long gid = (long long)blockIdx.x * blockDim.x + threadIdx.x;
    long long eg = gid >> 2;
    int sub = (int)(gid & 3);
    if (eg >= (long long)(ES + ED)) return;

    bool spatial = (eg < ES);
    int e = spatial ? (int)eg : (int)(eg - ES);
    const int* eidx = spatial ? si : di;
    int nE = spatial ? ES : ED;
    int src = eidx[e];
    int dst = eidx[nE + e];

    uint4 psr = *reinterpret_cast<const uint4*>(&g_Ps[(size_t)src * TT + sub * 8]);
    uint4 pdr = *reinterpret_cast<const uint4*>(&g_Pd[(size_t)dst * TT + sub * 8]);
    const __half2* ph = reinterpret_cast<const __half2*>(&psr);
    const __half2* qh = reinterpret_cast<const __half2*>(&pdr);

    float th[8];
#pragma unroll
    for (int j = 0; j < 4; j++) {
        float2 a = __half22float2(ph[j]);
        float2 b = __half22float2(qh[j]);
        float bt0 = b_trans[sub * 8 + 2 * j];
        float bt1 = b_trans[sub * 8 + 2 * j + 1];
        th[2 * j]     = fast_tanh(a.x + b.x + bt0);
        th[2 * j + 1] = fast_tanh(a.y + b.y + bt1);
    }

    float part = 0.f;
    if (spatial) {
        const float* w = &Wpos[4 + sub * 8];
#pragma unroll
        for (int j = 0; j < 8; j++) part += th[j] * w[j];
        if (sub == 0) {
            float4 a = *reinterpret_cast<const float4*>(&sattr[(size_t)e * 4]);
            part += a.x * Wpos[0] + a.y * Wpos[1] + a.z * Wpos[2] + a.w * Wpos[3];
        }
    } else {
        const float* w = &Wdom[1 + sub * 8];
#pragma unroll
        for (int j = 0; j < 8; j++) part += th[j] * w[j];
        if (sub == 0) part += dattr[e] * Wdom[0];
    }

    part += __shfl_xor_sync(0xFFFFFFFFu, part, 1);
    part += __shfl_xor_sync(0xFFFFFFFFu, part, 2);

    float logit = part + (spatial ? bpos[0] : bdom[0]);
    float ew = 1.f / (1.f + __expf(-logit));
    if (sub == 0) { if (spatial) g_ew_s[e] = ew; else g_ew_d[e] = ew; }

    // ---- fused round-1 propagation (lanes 0,1 of the quad) ----
    if (sub < 2) {
        const __half* c = spatial ? g_c16pos : g_c16dom;
        float* n = spatial ? g_n32pos : g_n32dom;
        uint4 sr = *reinterpret_cast<const uint4*>(&c[(size_t)src * MDIM + sub * 8]);
        uint4 dr = *reinterpret_cast<const uint4*>(&c[(size_t)dst * MDIM + sub * 8]);
        const __half2* sh = reinterpret_cast<const __half2*>(&sr);
        const __half2* dh = reinterpret_cast<const __half2*>(&dr);
        unsigned int* dn = reinterpret_cast<unsigned int*>(&n[(size_t)dst * MDIM + sub * 8]);
#pragma unroll
        for (int j = 0; j < 4; j++) {
            float2 s = __half22float2(sh[j]);
            float2 d = __half22float2(dh[j]);
            float v0 = s.x * ew, v1 = s.y * ew;
            if (v0 > d.x) atomicMax(dn + 2 * j + 0, __float_as_uint(v0));
            if (v1 > d.y) atomicMax(dn + 2 * j + 1, __float_as_uint(v1));
        }
    }
}

// ---------------- kernel 4: convert n32 -> c16 (both branches) ------------
__global__ void convert_kernel() {
    int i = blockIdx.x * blockDim.x + threadIdx.x;   // float4 index
    const int n4 = NN * MDIM / 4;
    if (i >= n4) return;
    float4 p = reinterpret_cast<const float4*>(g_n32pos)[i];
    float4 d = reinterpret_cast<const float4*>(g_n32dom)[i];
    __half2 p0 = __floats2half2_rn(p.x, p.y);
    __half2 p1 = __floats2half2_rn(p.z, p.w);
    __half2 d0 = __floats2half2_rn(d.x, d.y);
    __half2 d1 = __floats2half2_rn(d.z, d.w);
    reinterpret_cast<uint2*>(g_c16pos)[i] =
        make_uint2(*reinterpret_cast<unsigned*>(&p0), *reinterpret_cast<unsigned*>(&p1));
    reinterpret_cast<uint2*>(g_c16dom)[i] =
        make_uint2(*reinterpret_cast<unsigned*>(&d0), *reinterpret_cast<unsigned*>(&d1));
}

// ---------------- kernel 5: propagation rounds 2-3 (2 lanes/edge) ---------
__global__ void prop_kernel(const int* __restrict__ si, const int* __restrict__ di) {
    long long t = (long long)blockIdx.x * blockDim.x + threadIdx.x;
    long long p = t >> 1;
    int sub = (int)(t & 1);
    if (p >= (long long)(ES + ED)) return;

    const __half* c;
    float* n;
    int src, dst;
    float ew;
    if (p < ES) {
        int ei = (int)p;
        src = si[ei]; dst = si[ES + ei];
        ew = g_ew_s[ei];
        c = g_c16pos; n = g_n32pos;
    } else {
        int ei = (int)(p - ES);
        src = di[ei]; dst = di[ED + ei];
        ew = g_ew_d[ei];
        c = g_c16dom; n = g_n32dom;
    }

    uint4 sr = *reinterpret_cast<const uint4*>(&c[(size_t)src * MDIM + sub * 8]);
    uint4 dr = *reinterpret_cast<const uint4*>(&c[(size_t)dst * MDIM + sub * 8]);
    const __half2* sh = reinterpret_cast<const __half2*>(&sr);
    const __half2* dh = reinterpret_cast<const __half2*>(&dr);
    unsigned int* dn = reinterpret_cast<unsigned int*>(&n[(size_t)dst * MDIM + sub * 8]);

#pragma unroll
    for (int j = 0; j < 4; j++) {
        float2 s = __half22float2(sh[j]);
        float2 d = __half22float2(dh[j]);
        float v0 = s.x * ew, v1 = s.y * ew;
        if (v0 > d.x) atomicMax(dn + 2 * j + 0, __float_as_uint(v0));
        if (v1 > d.y) atomicMax(dn + 2 * j + 1, __float_as_uint(v1));
    }
}

// ---------------- kernel 6: final max --------------------------------------
__global__ void final_kernel(const float* __restrict__ mask, float* __restrict__ out) {
    int i = blockIdx.x * blockDim.x + threadIdx.x;
    const int n4 = NN * MDIM / 4;
    if (i >= n4) return;
    float4 m = reinterpret_cast<const float4*>(mask)[i];
    float4 p = reinterpret_cast<const float4*>(g_n32pos)[i];
    float4 d = reinterpret_cast<const float4*>(g_n32dom)[i];
    float4 r;
    r.x = fmaxf(m.x, fmaxf(p.x, d.x));
    r.y = fmaxf(m.y, fmaxf(p.y, d.y));
    r.z = fmaxf(m.z, fmaxf(p.z, d.z));
    r.w = fmaxf(m.w, fmaxf(p.w, d.w));
    reinterpret_cast<float4*>(out)[i] = r;
}

// ---------------- launch -------------------------------------------------
extern "C" void kernel_launch(void* const* d_in, const int* in_sizes, int n_in,
                              void* d_out, int out_size) {
    const float* x     = (const float*)d_in[0];
    const float* mask  = (const float*)d_in[1];
    const int*   si    = (const int*)d_in[2];
    const int*   di    = (const int*)d_in[3];
    const float* sattr = (const float*)d_in[4];
    const float* dattr = (const float*)d_in[5];
    const float* Wt    = (const float*)d_in[6];
    const float* bt    = (const float*)d_in[7];
    const float* Wpos  = (const float*)d_in[8];
    const float* bpos  = (const float*)d_in[9];
    const float* Wdom  = (const float*)d_in[10];
    const float* bdom  = (const float*)d_in[11];
    float* out = (float*)d_out;

    const int n4 = NN * MDIM / 4;
    const int cgrid = (n4 + 255) / 256;

    // 1. HMMA node projections (64 nodes/block)
    proj_kernel<<<(NN + 63) / 64, 128>>>(x, Wt);

    // 2. init: mask -> fp32 accumulators + fp16 mirrors
    init_kernel<<<cgrid, 256>>>(mask);

    // 3. fused gate + propagation round 1 (4 lanes/edge)
    {
        long long threads = (long long)(ES + ED) * 4;
        int blk = 256;
        long long grid = (threads + blk - 1) / blk;
        ewprop_kernel<<<(unsigned)grid, blk>>>(si, di, sattr, dattr, bt, Wpos, bpos, Wdom, bdom);
    }

    // 4. rounds 2-3: convert / prop / convert / prop
    {
        long long threads = (long long)(ES + ED) * 2;
        int blk = 256;
        long long grid = (threads + blk - 1) / blk;

        convert_kernel<<<cgrid, 256>>>();
        prop_kernel<<<(unsigned)grid, blk>>>(si, di);
        convert_kernel<<<cgrid, 256>>>();
        prop_kernel<<<(unsigned)grid, blk>>>(si, di);
    }

    // 5. final: max(mask, pos, dom)
    final_kernel<<<cgrid, 256>>>(mask, out);
}

// round 8
// speedup vs baseline: 1.7972x; 1.0513x over previous
#include <cuda_runtime.h>
#include <cuda_fp16.h>
#include <cstdint>

#define NN     100000
#define HH     128
#define TT     32
#define MDIM   16
#define ES     600000
#define ED     600000

// ---------------- scratch ----------------
__device__ __align__(16) __half g_Ps[NN * TT];   // fp16 x@W[:H]
__device__ __align__(16) __half g_Pd[NN * TT];   // fp16 x@W[H:] + b_trans
__device__ float g_ew_s[ES];
__device__ float g_ew_d[ED];
// propagation state: fp32 accumulator (atomics) + fp16 read mirror
__device__ __align__(16) float  g_n32pos[NN * MDIM];
__device__ __align__(16) float  g_n32dom[NN * MDIM];
__device__ __align__(16) __half g_c16pos[NN * MDIM];
__device__ __align__(16) __half g_c16dom[NN * MDIM];

// ---------------- helpers ----------------
__device__ __forceinline__ float fast_tanh(float s) {
    float r; asm("tanh.approx.f32 %0, %1;" : "=f"(r) : "f"(s)); return r;
}
__device__ __forceinline__ unsigned su32(const void* p) {
    return (unsigned)__cvta_generic_to_shared(p);
}

// ---------------- kernel 1: HMMA node projections --------------------------
// [NN,128] @ [128,64] fp16 (cols 0-31 = W[:128] -> Ps, 32-63 = W[128:] -> Pd).
// b_trans is folded into Pd at store time.
#define XS_STRIDE 136
#define WP_STRIDE 72

__global__ void __launch_bounds__(128) proj_kernel(const float* __restrict__ x,
                                                   const float* __restrict__ Wt,
                                                   const float* __restrict__ bt) {
    __shared__ __align__(16) __half Wp[128 * WP_STRIDE];
    __shared__ __align__(16) __half xs[64 * XS_STRIDE];
    int tid = threadIdx.x;
    int n0 = blockIdx.x * 64;

    for (int i = tid; i < 128 * 64; i += 128) {
        int h = i >> 6, j = i & 63;
        float w = (j < 32) ? Wt[h * 32 + j] : Wt[(128 + h) * 32 + (j - 32)];
        Wp[h * WP_STRIDE + j] = __float2half_rn(w);
    }
    for (int i = tid; i < 64 * 32; i += 128) {
        int r = i >> 5, c4 = i & 31;
        int node = n0 + r;
        float4 v = (node < NN)
                 ? reinterpret_cast<const float4*>(x)[(size_t)node * 32 + c4]
                 : make_float4(0.f, 0.f, 0.f, 0.f);
        *reinterpret_cast<__half2*>(&xs[r * XS_STRIDE + c4 * 4])     = __floats2half2_rn(v.x, v.y);
        *reinterpret_cast<__half2*>(&xs[r * XS_STRIDE + c4 * 4 + 2]) = __floats2half2_rn(v.z, v.w);
    }
    __syncthreads();

    int warp = tid >> 5, lane = tid & 31;
    int wb = warp * 16;

    float acc[8][4];
#pragma unroll
    for (int nt = 0; nt < 8; nt++)
#pragma unroll
        for (int j = 0; j < 4; j++) acc[nt][j] = 0.f;

    int a_row = wb + (lane & 15);
    int a_coff = (lane >> 4) * 8;
    int b_row = (lane & 15);

#pragma unroll
    for (int k = 0; k < 8; k++) {
        unsigned a0, a1, a2, a3;
        unsigned addrA = su32(&xs[a_row * XS_STRIDE + k * 16 + a_coff]);
        asm volatile("ldmatrix.sync.aligned.m8n8.x4.shared.b16 {%0,%1,%2,%3}, [%4];"
                     : "=r"(a0), "=r"(a1), "=r"(a2), "=r"(a3) : "r"(addrA));
#pragma unroll
        for (int nt = 0; nt < 8; nt++) {
            unsigned b0, b1;
            unsigned addrB = su32(&Wp[(k * 16 + b_row) * WP_STRIDE + nt * 8]);
            asm volatile("ldmatrix.sync.aligned.m8n8.x2.trans.shared.b16 {%0,%1}, [%2];"
                         : "=r"(b0), "=r"(b1) : "r"(addrB));
            asm volatile("mma.sync.aligned.m16n8k16.row.col.f32.f16.f16.f32 "
                         "{%0,%1,%2,%3}, {%4,%5,%6,%7}, {%8,%9}, {%0,%1,%2,%3};"
                         : "+f"(acc[nt][0]), "+f"(acc[nt][1]), "+f"(acc[nt][2]), "+f"(acc[nt][3])
                         : "r"(a0), "r"(a1), "r"(a2), "r"(a3), "r"(b0), "r"(b1));
        }
    }

    int row_l = wb + (lane >> 2);
    int col0 = (lane & 3) * 2;
#pragma unroll
    for (int nt = 0; nt < 8; nt++) {
        bool isPs = (nt < 4);
        __half* base = isPs ? g_Ps : g_Pd;
        int cc = isPs ? (nt * 8 + col0) : (nt * 8 + col0 - 32);
        float b0 = isPs ? 0.f : bt[cc];
        float b1 = isPs ? 0.f : bt[cc + 1];
        int nodeA = n0 + row_l;
        int nodeB = nodeA + 8;
        if (nodeA < NN)
            *reinterpret_cast<__half2*>(&base[(size_t)nodeA * TT + cc]) =
                __floats2half2_rn(acc[nt][0] + b0, acc[nt][1] + b1);
        if (nodeB < NN)
            *reinterpret_cast<__half2*>(&base[(size_t)nodeB * TT + cc]) =
                __floats2half2_rn(acc[nt][2] + b0, acc[nt][3] + b1);
    }
}

// ---------------- kernel 2: init: mask -> n32 (fp32) + c16 (fp16) ---------
__global__ void init_kernel(const float* __restrict__ mask) {
    int i = blockIdx.x * blockDim.x + threadIdx.x;
    const int n4 = NN * MDIM / 4;
    if (i >= n4) return;
    float4 v = reinterpret_cast<const float4*>(mask)[i];
    reinterpret_cast<float4*>(g_n32pos)[i] = v;
    reinterpret_cast<float4*>(g_n32dom)[i] = v;
    __half2 h0 = __floats2half2_rn(v.x, v.y);
    __half2 h1 = __floats2half2_rn(v.z, v.w);
    uint2 packed = make_uint2(*reinterpret_cast<unsigned*>(&h0), *reinterpret_cast<unsigned*>(&h1));
    reinterpret_cast<uint2*>(g_c16pos)[i] = packed;
    reinterpret_cast<uint2*>(g_c16dom)[i] = packed;
}

// ---------------- kernel 3: FUSED gate + propagation round 1 ---------------
// 4 lanes/edge: gate over 32 channels (bias pre-folded into Pd), quad-reduce,
// then ALL 4 lanes do the round-1 filtered propagation (4 channels each).
__global__ void ewprop_kernel(const int* __restrict__ si, const int* __restrict__ di,
                              const float* __restrict__ sattr, const float* __restrict__ dattr,
                              const float* __restrict__ Wpos, const float* __restrict__ bpos,
                              const float* __restrict__ Wdom, const float* __restrict__ bdom) {
    long long gid = (long long)blockIdx.x * blockDim.x + threadIdx.x;
    long long eg = gid >> 2;
    int sub = (int)(gid & 3);
    if (eg >= (long long)(ES + ED)) return;

    bool spatial = (eg < ES);
    int e = spatial ? (int)eg : (int)(eg - ES);
    const int* eidx = spatial ? si : di;
    int nE = spatial ? ES : ED;
    int src = eidx[e];
    int dst = eidx[nE + e];

    uint4 psr = *reinterpret_cast<const uint4*>(&g_Ps[(size_t)src * TT + sub * 8]);
    uint4 pdr = *reinterpret_cast<const uint4*>(&g_Pd[(size_t)dst * TT + sub * 8]);
    const __half2* ph = reinterpret_cast<const __half2*>(&psr);
    const __half2* qh = reinterpret_cast<const __half2*>(&pdr);

    float th[8];
#pragma unroll
    for (int j = 0; j < 4; j++) {
        float2 a = __half22float2(ph[j]);
        float2 b = __half22float2(qh[j]);
        th[2 * j]     = fast_tanh(a.x + b.x);
        th[2 * j + 1] = fast_tanh(a.y + b.y);
    }

    float part = 0.f;
    if (spatial) {
        const float* w = &Wpos[4 + sub * 8];
#pragma unroll
        for (int j = 0; j < 8; j++) part += th[j] * w[j];
        if (sub == 0) {
            float4 a = *reinterpret_cast<const float4*>(&sattr[(size_t)e * 4]);
            part += a.x * Wpos[0] + a.y * Wpos[1] + a.z * Wpos[2] + a.w * Wpos[3];
        }
    } else {
        const float* w = &Wdom[1 + sub * 8];
#pragma unroll
        for (int j = 0; j < 8; j++) part += th[j] * w[j];
        if (sub == 0) part += dattr[e] * Wdom[0];
    }

    part += __shfl_xor_sync(0xFFFFFFFFu, part, 1);
    part += __shfl_xor_sync(0xFFFFFFFFu, part, 2);

    float logit = part + (spatial ? bpos[0] : bdom[0]);
    float ew = 1.f / (1.f + __expf(-logit));
    if (sub == 0) { if (spatial) g_ew_s[e] = ew; else g_ew_d[e] = ew; }

    // ---- fused round-1 propagation: 4 lanes x 4 channels ----
    {
        const __half* c = spatial ? g_c16pos : g_c16dom;
        float* n = spatial ? g_n32pos : g_n32dom;
        uint2 sr = *reinterpret_cast<const uint2*>(&c[(size_t)src * MDIM + sub * 4]);
        uint2 dr = *reinterpret_cast<const uint2*>(&c[(size_t)dst * MDIM + sub * 4]);
        const __half2* sh = reinterpret_cast<const __half2*>(&sr);
        const __half2* dh = reinterpret_cast<const __half2*>(&dr);
        unsigned int* dn = reinterpret_cast<unsigned int*>(&n[(size_t)dst * MDIM + sub * 4]);
#pragma unroll
        for (int j = 0; j < 2; j++) {
            float2 s = __half22float2(sh[j]);
            float2 d = __half22float2(dh[j]);
            float v0 = s.x * ew, v1 = s.y * ew;
            if (v0 > d.x) atomicMax(dn + 2 * j + 0, __float_as_uint(v0));
            if (v1 > d.y) atomicMax(dn + 2 * j + 1, __float_as_uint(v1));
        }
    }
}

// ---------------- kernel 4: convert n32 -> c16 (both branches) ------------
__global__ void convert_kernel() {
    int i = blockIdx.x * blockDim.x + threadIdx.x;
    const int n4 = NN * MDIM / 4;
    if (i >= n4) return;
    float4 p = reinterpret_cast<const float4*>(g_n32pos)[i];
    float4 d = reinterpret_cast<const float4*>(g_n32dom)[i];
    __half2 p0 = __floats2half2_rn(p.x, p.y);
    __half2 p1 = __floats2half2_rn(p.z, p.w);
    __half2 d0 = __floats2half2_rn(d.x, d.y);
    __half2 d1 = __floats2half2_rn(d.z, d.w);
    reinterpret_cast<uint2*>(g_c16pos)[i] =
        make_uint2(*reinterpret_cast<unsigned*>(&p0), *reinterpret_cast<unsigned*>(&p1));
    reinterpret_cast<uint2*>(g_c16dom)[i] =
        make_uint2(*reinterpret_cast<unsigned*>(&d0), *reinterpret_cast<unsigned*>(&d1));
}

// ---------------- kernel 5: propagation rounds 2-3 -------------------------
// 2 lanes per edge, 2 edges per thread (one spatial + one dom), all four row
// loads front-batched for MLP=4. ES == ED is assumed by the pairing.
__global__ void prop_kernel(const int* __restrict__ si, const int* __restrict__ di) {
    long long t = (long long)blockIdx.x * blockDim.x + threadIdx.x;
    if (t >= (long long)ES * 2) return;
    int p = (int)(t >> 1);       // edge id in each set
    int sub = (int)(t & 1);      // half-row (8 channels)

    int s0 = si[p], d0 = si[ES + p];
    int s1 = di[p], d1 = di[ED + p];
    float ew0 = g_ew_s[p];
    float ew1 = g_ew_d[p];

    uint4 sr0 = *reinterpret_cast<const uint4*>(&g_c16pos[(size_t)s0 * MDIM + sub * 8]);
    uint4 dr0 = *reinterpret_cast<const uint4*>(&g_c16pos[(size_t)d0 * MDIM + sub * 8]);
    uint4 sr1 = *reinterpret_cast<const uint4*>(&g_c16dom[(size_t)s1 * MDIM + sub * 8]);
    uint4 dr1 = *reinterpret_cast<const uint4*>(&g_c16dom[(size_t)d1 * MDIM + sub * 8]);

    {
        const __half2* sh = reinterpret_cast<const __half2*>(&sr0);
        const __half2* dh = reinterpret_cast<const __half2*>(&dr0);
        unsigned int* dn = reinterpret_cast<unsigned int*>(&g_n32pos[(size_t)d0 * MDIM + sub * 8]);
#pragma unroll
        for (int j = 0; j < 4; j++) {
            float2 s = __half22float2(sh[j]);
            float2 d = __half22float2(dh[j]);
            float v0 = s.x * ew0, v1 = s.y * ew0;
            if (v0 > d.x) atomicMax(dn + 2 * j + 0, __float_as_uint(v0));
            if (v1 > d.y) atomicMax(dn + 2 * j + 1, __float_as_uint(v1));
        }
    }
    {
        const __half2* sh = reinterpret_cast<const __half2*>(&sr1);
        const __half2* dh = reinterpret_cast<const __half2*>(&dr1);
        unsigned int* dn = reinterpret_cast<unsigned int*>(&g_n32dom[(size_t)d1 * MDIM + sub * 8]);
#pragma unroll
        for (int j = 0; j < 4; j++) {
            float2 s = __half22float2(sh[j]);
            float2 d = __half22float2(dh[j]);
            float v0 = s.x * ew1, v1 = s.y * ew1;
            if (v0 > d.x) atomicMax(dn + 2 * j + 0, __float_as_uint(v0));
            if (v1 > d.y) atomicMax(dn + 2 * j + 1, __float_as_uint(v1));
        }
    }
}

// ---------------- kernel 6: final max --------------------------------------
__global__ void final_kernel(const float* __restrict__ mask, float* __restrict__ out) {
    int i = blockIdx.x * blockDim.x + threadIdx.x;
    const int n4 = NN * MDIM / 4;
    if (i >= n4) return;
    float4 m = reinterpret_cast<const float4*>(mask)[i];
    float4 p = reinterpret_cast<const float4*>(g_n32pos)[i];
    float4 d = reinterpret_cast<const float4*>(g_n32dom)[i];
    float4 r;
    r.x = fmaxf(m.x, fmaxf(p.x, d.x));
    r.y = fmaxf(m.y, fmaxf(p.y, d.y));
    r.z = fmaxf(m.z, fmaxf(p.z, d.z));
    r.w = fmaxf(m.w, fmaxf(p.w, d.w));
    reinterpret_cast<float4*>(out)[i] = r;
}

// ---------------- launch -------------------------------------------------
extern "C" void kernel_launch(void* const* d_in, const int* in_sizes, int n_in,
                              void* d_out, int out_size) {
    const float* x     = (const float*)d_in[0];
    const float* mask  = (const float*)d_in[1];
    const int*   si    = (const int*)d_in[2];
    const int*   di    = (const int*)d_in[3];
    const float* sattr = (const float*)d_in[4];
    const float* dattr = (const float*)d_in[5];
    const float* Wt    = (const float*)d_in[6];
    const float* bt    = (const float*)d_in[7];
    const float* Wpos  = (const float*)d_in[8];
    const float* bpos  = (const float*)d_in[9];
    const float* Wdom  = (const float*)d_in[10];
    const float* bdom  = (const float*)d_in[11];
    float* out = (float*)d_out;

    const int n4 = NN * MDIM / 4;
    const int cgrid = (n4 + 255) / 256;

    // 1. HMMA node projections (bias folded into Pd)
    proj_kernel<<<(NN + 63) / 64, 128>>>(x, Wt, bt);

    // 2. init: mask -> fp32 accumulators + fp16 mirrors
    init_kernel<<<cgrid, 256>>>(mask);

    // 3. fused gate + propagation round 1
    {
        long long threads = (long long)(ES + ED) * 4;
        int blk = 256;
        long long grid = (threads + blk - 1) / blk;
        ewprop_kernel<<<(unsigned)grid, blk>>>(si, di, sattr, dattr, Wpos, bpos, Wdom, bdom);
    }

    // 4. rounds 2-3: convert / prop / convert / prop
    {
        long long threads = (long long)ES * 2;   // 2 edges (one per set) per thread
        int blk = 256;
        long long grid = (threads + blk - 1) / blk;

        convert_kernel<<<cgrid, 256>>>();
        prop_kernel<<<(unsigned)grid, blk>>>(si, di);
        convert_kernel<<<cgrid, 256>>>();
        prop_kernel<<<(unsigned)grid, blk>>>(si, di);
    }

    // 5. final: max(mask, pos, dom)
    final_kernel<<<cgrid, 256>>>(mask, out);
}